// round 3
// baseline (speedup 1.0000x reference)
#include <cuda_runtime.h>
#include <cuda_bf16.h>

// out[i,c] = sum_k (neigh[i,k]>=0 ? data[neigh[i,k],c] : 0) * w[k,c]
// N=200000, K=27, C=64.
// L1-wavefront-optimized: 4 points per thread (weight LDS amortized 4x),
// int4 index loads from padded smem, 16 threads * float4 per point row.

#define KK 27
#define CV 16          // C/4 float4 per row
#define QP 4           // points per thread
#define TPB 256
#define PTSBLK 64      // (TPB/16) * QP points per block
#define NPAD 28        // padded ints per point (16B-aligned rows)

#define FMA4(ACC, D, W) \
    ACC.x = fmaf(D.x, W.x, ACC.x); \
    ACC.y = fmaf(D.y, W.y, ACC.y); \
    ACC.z = fmaf(D.z, W.z, ACC.z); \
    ACC.w = fmaf(D.w, W.w, ACC.w);

#define GSTEP(K, COMP) \
    { \
        const float4 wv = s_w[(K) * CV + lane]; \
        const int a0 = i0.COMP, a1 = i1.COMP, a2 = i2.COMP, a3 = i3.COMP; \
        if (a0 >= 0) { const float4 d = __ldg(&data[(size_t)a0 * CV + lane]); FMA4(acc0, d, wv) } \
        if (a1 >= 0) { const float4 d = __ldg(&data[(size_t)a1 * CV + lane]); FMA4(acc1, d, wv) } \
        if (a2 >= 0) { const float4 d = __ldg(&data[(size_t)a2 * CV + lane]); FMA4(acc2, d, wv) } \
        if (a3 >= 0) { const float4 d = __ldg(&data[(size_t)a3 * CV + lane]); FMA4(acc3, d, wv) } \
    }

__global__ __launch_bounds__(TPB)
void octree_dwconv_kernel(const float4* __restrict__ data,    // [N][16] float4
                          const float4* __restrict__ w4g,     // [27*16] float4
                          const int*    __restrict__ neigh,   // [N][27]
                          float4*       __restrict__ out)     // [N][16]
{
    __shared__ float4 s_w[KK * CV];          // 6912 B
    __shared__ int    s_n[PTSBLK * NPAD];    // 7168 B (padded, int4-aligned rows)

    const int tid  = threadIdx.x;
    const int base = blockIdx.x * PTSBLK;

    // Stage weights (432 float4)
    #pragma unroll
    for (int i = tid; i < KK * CV; i += TPB)
        s_w[i] = w4g[i];

    // Stage 64*27 neighbor indices into padded layout [64][28]
    #pragma unroll
    for (int i = tid; i < PTSBLK * KK; i += TPB) {
        const int p = i / KK;
        const int k = i - p * KK;
        s_n[p * NPAD + k] = neigh[base * KK + i];
    }
    __syncthreads();

    const int lane = tid & 15;       // float4 column 0..15
    const int g    = tid >> 4;       // point group 0..15
    const int p0   = g * QP;         // local point base

    const int4* s_n4 = reinterpret_cast<const int4*>(s_n);   // [64][7]

    float4 acc0 = make_float4(0.f, 0.f, 0.f, 0.f);
    float4 acc1 = acc0, acc2 = acc0, acc3 = acc0;

    #pragma unroll
    for (int kc = 0; kc < 7; kc++) {
        // 4 int4 loads cover k = 4*kc .. 4*kc+3 for each of this thread's 4 points
        const int4 i0 = s_n4[(p0 + 0) * 7 + kc];
        const int4 i1 = s_n4[(p0 + 1) * 7 + kc];
        const int4 i2 = s_n4[(p0 + 2) * 7 + kc];
        const int4 i3 = s_n4[(p0 + 3) * 7 + kc];

        const int kb = kc * 4;
        GSTEP(kb + 0, x)
        GSTEP(kb + 1, y)
        GSTEP(kb + 2, z)
        if (kc < 6) {            // k=27 doesn't exist (27 = 6*4 + 3)
            GSTEP(kb + 3, w)
        }
    }

    const size_t ob = (size_t)(base + p0) * CV + lane;
    out[ob + 0 * CV] = acc0;
    out[ob + 1 * CV] = acc1;
    out[ob + 2 * CV] = acc2;
    out[ob + 3 * CV] = acc3;
}

extern "C" void kernel_launch(void* const* d_in, const int* in_sizes, int n_in,
                              void* d_out, int out_size) {
    const float4* data    = (const float4*)d_in[0];   // [N,64] fp32
    const float4* w4g     = (const float4*)d_in[1];   // [27,1,64] fp32
    const int*    neigh   = (const int*)d_in[2];      // [N,27] int32
    float4* out = (float4*)d_out;

    const int N = in_sizes[0] / 64;                   // 200000
    const int grid = (N + PTSBLK - 1) / PTSBLK;       // 3125 exactly

    octree_dwconv_kernel<<<grid, TPB>>>(data, w4g, neigh, out);
}

// round 6
// speedup vs baseline: 1.5395x; 1.5395x over previous
#include <cuda_runtime.h>
#include <cuda_bf16.h>

// out[i,c] = sum_k (neigh[i,k]>=0 ? data[neigh[i,k],c] : 0) * w[k,c]
// N=200000, K=27, C=64.
// QP=2 points/thread: weight LDS amortized 2x, int4 index loads,
// 32-bit address math, high occupancy to stay L1-throughput-bound.

#define KK 27
#define CV 16          // C/4 float4 per row
#define QP 2           // points per thread
#define TPB 256
#define GRPS 16        // thread groups per block (TPB/16)
#define PTSBLK 32      // GRPS * QP
#define NPAD 28        // padded ints per point row (16B aligned)

#define FMA4(ACC, D, W) \
    ACC.x = fmaf(D.x, W.x, ACC.x); \
    ACC.y = fmaf(D.y, W.y, ACC.y); \
    ACC.z = fmaf(D.z, W.z, ACC.z); \
    ACC.w = fmaf(D.w, W.w, ACC.w);

#define GSTEP(K, COMP) \
    { \
        const float4 wv = s_w[(K) * CV + lane]; \
        const int a0 = i0.COMP, a1 = i1.COMP; \
        if (a0 >= 0) { const float4 d = __ldg(data + (unsigned)a0 * CV + lane); FMA4(acc0, d, wv) } \
        if (a1 >= 0) { const float4 d = __ldg(data + (unsigned)a1 * CV + lane); FMA4(acc1, d, wv) } \
    }

__global__ __launch_bounds__(TPB)
void octree_dwconv_kernel(const float4* __restrict__ data,    // [N][16] float4
                          const float4* __restrict__ w4g,     // [27*16] float4
                          const int*    __restrict__ neigh,   // [N][27]
                          float4*       __restrict__ out)     // [N][16]
{
    __shared__ float4 s_w[KK * CV];          // 6912 B
    __shared__ int    s_n[PTSBLK * NPAD];    // 32*28*4 = 3584 B

    const int tid  = threadIdx.x;
    const int base = blockIdx.x * PTSBLK;

    // Stage weights (432 float4)
    #pragma unroll
    for (int i = tid; i < KK * CV; i += TPB)
        s_w[i] = w4g[i];

    // Stage 32*27 neighbor indices into padded layout [32][28]
    #pragma unroll
    for (int i = tid; i < PTSBLK * KK; i += TPB) {
        const int p = i / KK;
        const int k = i - p * KK;
        s_n[p * NPAD + k] = neigh[base * KK + i];
    }
    __syncthreads();

    const int lane = tid & 15;       // float4 column 0..15
    const int g    = tid >> 4;       // group 0..15
    const int p0   = g * QP;         // local point base

    const int4* s_n4 = reinterpret_cast<const int4*>(s_n);   // [32][7]

    float4 acc0 = make_float4(0.f, 0.f, 0.f, 0.f);
    float4 acc1 = acc0;

    #pragma unroll
    for (int kc = 0; kc < 7; kc++) {
        const int4 i0 = s_n4[(p0 + 0) * 7 + kc];
        const int4 i1 = s_n4[(p0 + 1) * 7 + kc];

        const int kb = kc * 4;
        GSTEP(kb + 0, x)
        GSTEP(kb + 1, y)
        GSTEP(kb + 2, z)
        if (kc < 6) {            // k = 27 doesn't exist (27 = 6*4 + 3)
            GSTEP(kb + 3, w)
        }
    }

    const unsigned ob = (unsigned)(base + p0) * CV + lane;
    out[ob + 0 * CV] = acc0;
    out[ob + 1 * CV] = acc1;
}

extern "C" void kernel_launch(void* const* d_in, const int* in_sizes, int n_in,
                              void* d_out, int out_size) {
    const float4* data    = (const float4*)d_in[0];   // [N,64] fp32
    const float4* w4g     = (const float4*)d_in[1];   // [27,1,64] fp32
    const int*    neigh   = (const int*)d_in[2];      // [N,27] int32
    float4* out = (float4*)d_out;

    const int N = in_sizes[0] / 64;                   // 200000
    const int grid = (N + PTSBLK - 1) / PTSBLK;       // 6250

    octree_dwconv_kernel<<<grid, TPB>>>(data, w4g, neigh, out);
}

// round 7
// speedup vs baseline: 1.6321x; 1.0602x over previous
#include <cuda_runtime.h>
#include <cuda_bf16.h>

// out[i,c] = sum_k (neigh[i,k]>=0 ? data[neigh[i,k],c] : 0) * w[k,c]
// N=200000, K=27, C=64.
// QP=2 points/thread, TPB=128 for 11 blocks/SM (~69% occ).
// Weights read directly via __ldg (hot in L1, same 2 wf/k/warp as LDS,
// zero staging cost). Smem used only for int4-aligned index repack.

#define KK 27
#define CV 16          // C/4 float4 per row
#define QP 2           // points per thread
#define TPB 128
#define GRPS 8         // TPB/16 thread groups
#define PTSBLK 16      // GRPS * QP
#define NPAD 28        // padded ints per point row (16B aligned)

#define FMA4(ACC, D, W) \
    ACC.x = fmaf(D.x, W.x, ACC.x); \
    ACC.y = fmaf(D.y, W.y, ACC.y); \
    ACC.z = fmaf(D.z, W.z, ACC.z); \
    ACC.w = fmaf(D.w, W.w, ACC.w);

#define GSTEP(K, COMP) \
    { \
        const float4 wv = __ldg(w4g + (K) * CV + lane); \
        const int a0 = i0.COMP, a1 = i1.COMP; \
        if (a0 >= 0) { const float4 d = __ldg(data + (unsigned)a0 * CV + lane); FMA4(acc0, d, wv) } \
        if (a1 >= 0) { const float4 d = __ldg(data + (unsigned)a1 * CV + lane); FMA4(acc1, d, wv) } \
    }

__global__ __launch_bounds__(TPB)
void octree_dwconv_kernel(const float4* __restrict__ data,    // [N][16] float4
                          const float4* __restrict__ w4g,     // [27*16] float4
                          const int*    __restrict__ neigh,   // [N][27]
                          float4*       __restrict__ out)     // [N][16]
{
    __shared__ int s_n[PTSBLK * NPAD];    // 16*28*4 = 1792 B

    const int tid  = threadIdx.x;
    const int base = blockIdx.x * PTSBLK;

    // Stage 16*27 neighbor indices into padded layout [16][28]
    #pragma unroll
    for (int i = tid; i < PTSBLK * KK; i += TPB) {
        const int p = i / KK;
        const int k = i - p * KK;
        s_n[p * NPAD + k] = neigh[base * KK + i];
    }
    __syncthreads();

    const int lane = tid & 15;       // float4 column 0..15
    const int g    = tid >> 4;       // group 0..7
    const int p0   = g * QP;         // local point base

    const int4* s_n4 = reinterpret_cast<const int4*>(s_n);   // [16][7]

    float4 acc0 = make_float4(0.f, 0.f, 0.f, 0.f);
    float4 acc1 = acc0;

    #pragma unroll
    for (int kc = 0; kc < 7; kc++) {
        const int4 i0 = s_n4[(p0 + 0) * 7 + kc];
        const int4 i1 = s_n4[(p0 + 1) * 7 + kc];

        const int kb = kc * 4;
        GSTEP(kb + 0, x)
        GSTEP(kb + 1, y)
        GSTEP(kb + 2, z)
        if (kc < 6) {            // k = 27 doesn't exist (27 = 6*4 + 3)
            GSTEP(kb + 3, w)
        }
    }

    const unsigned ob = (unsigned)(base + p0) * CV + lane;
    out[ob + 0 * CV] = acc0;
    out[ob + 1 * CV] = acc1;
}

extern "C" void kernel_launch(void* const* d_in, const int* in_sizes, int n_in,
                              void* d_out, int out_size) {
    const float4* data    = (const float4*)d_in[0];   // [N,64] fp32
    const float4* w4g     = (const float4*)d_in[1];   // [27,1,64] fp32
    const int*    neigh   = (const int*)d_in[2];      // [N,27] int32
    float4* out = (float4*)d_out;

    const int N = in_sizes[0] / 64;                   // 200000
    const int grid = (N + PTSBLK - 1) / PTSBLK;       // 12500

    octree_dwconv_kernel<<<grid, TPB>>>(data, w4g, neigh, out);
}